// round 2
// baseline (speedup 1.0000x reference)
#include <cuda_runtime.h>
#include <cstdint>
#include <math.h>

// ---------------- problem constants ----------------
#define NS    6400          // SAMPLE*SAMPLE patches per image
#define CCH   49            // PATCH*PATCH channels
#define IMGW  512
#define GW    169           // (512-7)/3 + 1 patch-grid size
#define EPSF  2.2204460492503131e-16f
#define LAMB  0.05f

// ---------------- device scratch (static; no runtime allocation) ----------------
__device__ int   g_base_t[NS];
__device__ int   g_base_r[NS];
__device__ float g_ymean[CCH];
__device__ float g_xf[CCH * NS];      // [c][p], channel-major
__device__ float g_yf[CCH * NS];
__device__ float g_d[(size_t)NS * NS];   // 163.84 MB distance matrix
__device__ unsigned long long g_amin[NS];
__device__ int   g_cnt[NS];
__device__ float g_rowloss[NS];

// ---------------- 1) grid-sample nearest indices (+ init amin/cnt) ----------------
__global__ void k_idx(const float* __restrict__ tfield, const float* __restrict__ rfield) {
    int i = blockIdx.x * blockDim.x + threadIdx.x;
    if (i < NS) { g_amin[i] = ~0ull; g_cnt[i] = 0; }
    if (i >= 2 * NS) return;
    const float* f = (i < NS) ? tfield : rfield;
    int p = (i < NS) ? i : (i - NS);
    float gx = __fadd_rn(__fmul_rn(f[2 * p + 0], 2.0f), -1.0f);
    float gy = __fadd_rn(__fmul_rn(f[2 * p + 1], 2.0f), -1.0f);
    float fx = __fmul_rn(__fadd_rn(__fmul_rn(__fadd_rn(gx, 1.0f), (float)GW), -1.0f), 0.5f);
    float fy = __fmul_rn(__fadd_rn(__fmul_rn(__fadd_rn(gy, 1.0f), (float)GW), -1.0f), 0.5f);
    int ix = (int)rintf(fx); ix = ix < 0 ? 0 : (ix > GW - 1 ? GW - 1 : ix);
    int iy = (int)rintf(fy); iy = iy < 0 ? 0 : (iy > GW - 1 ? GW - 1 : iy);
    int base = (iy * 3) * IMGW + ix * 3;   // top-left of 7x7 patch in image
    if (i < NS) g_base_t[p] = base; else g_base_r[p] = base;
}

// ---------------- 2) refer patch channel mean (deterministic tree) ----------------
__global__ void k_mean(const float* __restrict__ rimg) {
    int c = blockIdx.x;                     // 49 blocks
    int off = (c / 7) * IMGW + (c % 7);
    int t = threadIdx.x;
    float s = 0.0f;
    for (int p = t; p < NS; p += 256) s += rimg[g_base_r[p] + off];
    __shared__ float sm[256];
    sm[t] = s; __syncthreads();
    for (int st = 128; st; st >>= 1) { if (t < st) sm[t] += sm[t + st]; __syncthreads(); }
    if (t == 0) g_ymean[c] = sm[0] * (1.0f / (float)NS);
}

// ---------------- 3) centered + L2-normalized feature vectors ----------------
__global__ void k_feat(const float* __restrict__ timg, const float* __restrict__ rimg) {
    int p = blockIdx.x * 256 + threadIdx.x;           // gridDim.x = 25
    bool is_t = (blockIdx.y == 0);
    const float* img = is_t ? timg : rimg;
    int base = is_t ? g_base_t[p] : g_base_r[p];
    float* out = is_t ? g_xf : g_yf;
    float v[CCH];
    float sq = 0.0f;
#pragma unroll
    for (int c = 0; c < CCH; c++) {
        v[c] = img[base + (c / 7) * IMGW + (c % 7)] - g_ymean[c];
        sq += v[c] * v[c];
    }
    float inv = 1.0f / (sqrtf(sq) + EPSF);
#pragma unroll
    for (int c = 0; c < CCH; c++) out[c * NS + p] = v[c] * inv;
}

// ---------------- 4) GEMM: d = max((1 - xf^T yf)/2, 0), store + row argmin ----------------
// tiles: 128 rows (p) x 128 cols (q), 256 threads, 8x8 micro-tile, dynamic smem
__global__ void __launch_bounds__(256, 2) k_gemm() {
    extern __shared__ float sm[];
    float* As = sm;                // [49][128]
    float* Bs = sm + CCH * 128;    // [49][128]
    int by = blockIdx.y;   // 50 row tiles
    int bx = blockIdx.x;   // 50 col tiles
    int t = threadIdx.x;

    // vectorized tile loads (rows of g_xf/g_yf are 6400 floats; 128-col slices 16B-aligned)
    for (int i = t; i < CCH * 32; i += 256) {
        int k = i >> 5, m = (i & 31) << 2;
        *(float4*)&As[k * 128 + m] = *(const float4*)&g_xf[k * NS + by * 128 + m];
        *(float4*)&Bs[k * 128 + m] = *(const float4*)&g_yf[k * NS + bx * 128 + m];
    }
    __syncthreads();

    int tx = t & 15, ty = t >> 4;
    float acc[8][8];
#pragma unroll
    for (int i = 0; i < 8; i++)
#pragma unroll
        for (int j = 0; j < 8; j++) acc[i][j] = 0.0f;

#pragma unroll 1
    for (int k = 0; k < CCH; k++) {
        float4 a0 = *(const float4*)&As[k * 128 + ty * 8];
        float4 a1 = *(const float4*)&As[k * 128 + ty * 8 + 4];
        float4 b0 = *(const float4*)&Bs[k * 128 + tx * 8];
        float4 b1 = *(const float4*)&Bs[k * 128 + tx * 8 + 4];
        float a[8] = {a0.x, a0.y, a0.z, a0.w, a1.x, a1.y, a1.z, a1.w};
        float b[8] = {b0.x, b0.y, b0.z, b0.w, b1.x, b1.y, b1.z, b1.w};
#pragma unroll
        for (int i = 0; i < 8; i++)
#pragma unroll
            for (int j = 0; j < 8; j++) acc[i][j] += a[i] * b[j];
    }

    int row0 = by * 128 + ty * 8;
    int col0 = bx * 128 + tx * 8;
#pragma unroll
    for (int i = 0; i < 8; i++) {
        float dv[8];
        unsigned long long key = ~0ull;
#pragma unroll
        for (int j = 0; j < 8; j++) {
            float sim = acc[i][j];
            float dd = fmaxf(__fmul_rn(__fadd_rn(1.0f, -sim), 0.5f), 0.0f);
            dv[j] = dd;
            unsigned long long kk =
                ((unsigned long long)__float_as_uint(dd) << 32) | (unsigned)(col0 + j);
            key = (kk < key) ? kk : key;   // strict <  -> first-index tie break
        }
        float* dst = &g_d[(size_t)(row0 + i) * NS + col0];
        *(float4*)dst       = make_float4(dv[0], dv[1], dv[2], dv[3]);
        *(float4*)(dst + 4) = make_float4(dv[4], dv[5], dv[6], dv[7]);
#pragma unroll
        for (int off = 8; off; off >>= 1) {
            unsigned long long o = __shfl_down_sync(0xffffffffu, key, off, 16);
            key = (o < key) ? o : key;
        }
        if (tx == 0) atomicMin(&g_amin[row0 + i], key);
    }
}

// ---------------- 5) occurrence counts ----------------
__global__ void k_cnt() {
    int p = blockIdx.x * 256 + threadIdx.x;
    if (p < NS) {
        unsigned q = (unsigned)(g_amin[p] & 0xffffffffu);
        atomicAdd(&g_cnt[q], 1);
    }
}

// ---------------- 6) per-row min + sum-exp -> row loss ----------------
__global__ void __launch_bounds__(256) k_row() {
    __shared__ float sd[NS];        // 25.6 KB: d' row cache
    __shared__ float sr[8];
    int p = blockIdx.x;
    int t = threadIdx.x;
    const float4* drow = (const float4*)&g_d[(size_t)p * NS];

    // fused load + occurrence add + partial min
    float m = 3.4e38f;
    for (int j4 = t; j4 < NS / 4; j4 += 256) {
        float4 d4 = drow[j4];
        int j = j4 * 4;
        float a = d4.x + LAMB * (float)g_cnt[j + 0];
        float b = d4.y + LAMB * (float)g_cnt[j + 1];
        float c = d4.z + LAMB * (float)g_cnt[j + 2];
        float e = d4.w + LAMB * (float)g_cnt[j + 3];
        sd[j + 0] = a; sd[j + 1] = b; sd[j + 2] = c; sd[j + 3] = e;
        m = fminf(m, fminf(fminf(a, b), fminf(c, e)));
    }
#pragma unroll
    for (int o = 16; o; o >>= 1) m = fminf(m, __shfl_xor_sync(0xffffffffu, m, o));
    if ((t & 31) == 0) sr[t >> 5] = m;
    __syncthreads();
    if (t == 0) {
        float x = sr[0];
#pragma unroll
        for (int w = 1; w < 8; w++) x = fminf(x, sr[w]);
        sr[0] = x;
    }
    __syncthreads();
    m = sr[0];
    __syncthreads();

    float meps = __fadd_rn(m, EPSF);
    float inv = 1.0f / meps;

    // block sum of w = exp((1 - d'/(m+eps))*2)
    float s = 0.0f;
    for (int j = t; j < NS; j += 256) {
        float r = sd[j] * inv;
        s += __expf(__fmul_rn(__fadd_rn(1.0f, -r), 2.0f));
    }
#pragma unroll
    for (int o = 16; o; o >>= 1) s += __shfl_xor_sync(0xffffffffu, s, o);
    if ((t & 31) == 0) sr[t >> 5] = s;
    __syncthreads();
    if (t == 0) {
        float st = 0.0f;
#pragma unroll
        for (int w = 0; w < 8; w++) st += sr[w];
        float emax = __fmul_rn(__fadd_rn(1.0f, -__fmul_rn(m, inv)), 2.0f);
        g_rowloss[p] = logf(st) - emax;   // -log(CX)
    }
}

// ---------------- 7) final mean ----------------
__global__ void k_final(float* __restrict__ out) {
    int t = threadIdx.x;
    float s = 0.0f;
    for (int p = t; p < NS; p += 256) s += g_rowloss[p];
    __shared__ float sm[256];
    sm[t] = s; __syncthreads();
    for (int st = 128; st; st >>= 1) { if (t < st) sm[t] += sm[t + st]; __syncthreads(); }
    if (t == 0) out[0] = sm[0] * (1.0f / (float)NS);
}

// ---------------- host launch ----------------
extern "C" void kernel_launch(void* const* d_in, const int* in_sizes, int n_in,
                              void* d_out, int out_size) {
    (void)in_sizes; (void)n_in; (void)out_size;
    const float* timg   = (const float*)d_in[0];   // target_features [1,1,512,512]
    const float* rimg   = (const float*)d_in[1];   // refer_features  [1,1,512,512]
    const float* tfield = (const float*)d_in[2];   // target_field [1,80,80,2]
    const float* rfield = (const float*)d_in[3];   // refer_field  [1,80,80,2]
    float* out = (float*)d_out;

    const int GEMM_SMEM = 2 * CCH * 128 * (int)sizeof(float);   // 50176 B
    cudaFuncSetAttribute(k_gemm, cudaFuncAttributeMaxDynamicSharedMemorySize, GEMM_SMEM);

    k_idx  <<<50, 256>>>(tfield, rfield);
    k_mean <<<CCH, 256>>>(rimg);
    k_feat <<<dim3(25, 2), 256>>>(timg, rimg);
    k_gemm <<<dim3(50, 50), 256, GEMM_SMEM>>>();
    k_cnt  <<<25, 256>>>();
    k_row  <<<NS, 256>>>();
    k_final<<<1, 256>>>(out);
}

// round 3
// speedup vs baseline: 1.0397x; 1.0397x over previous
#include <cuda_runtime.h>
#include <cuda_fp16.h>
#include <cstdint>
#include <math.h>

// ---------------- problem constants ----------------
#define NS    6400          // SAMPLE*SAMPLE patches per image
#define CCH   49            // PATCH*PATCH channels
#define IMGW  512
#define GW    169           // (512-7)/3 + 1 patch-grid size
#define EPSF  2.2204460492503131e-16f
#define LAMB  0.05f

// ---------------- device scratch (static; no runtime allocation) ----------------
__device__ int   g_base_t[NS];
__device__ int   g_base_r[NS];
__device__ float g_ymean[CCH];
__device__ float g_xf[CCH * NS];      // [c][p], channel-major
__device__ float g_yf[CCH * NS];
__device__ __half g_dh[(size_t)NS * NS];   // 81.92 MB distance matrix (fp16)
__device__ unsigned long long g_amin[NS];
__device__ int   g_cnt[NS];
__device__ float g_rowloss[NS];

// ---------------- 1) grid-sample nearest indices (+ init amin/cnt) ----------------
__global__ void k_idx(const float* __restrict__ tfield, const float* __restrict__ rfield) {
    int i = blockIdx.x * blockDim.x + threadIdx.x;
    if (i < NS) { g_amin[i] = ~0ull; g_cnt[i] = 0; }
    if (i >= 2 * NS) return;
    const float* f = (i < NS) ? tfield : rfield;
    int p = (i < NS) ? i : (i - NS);
    float gx = __fadd_rn(__fmul_rn(f[2 * p + 0], 2.0f), -1.0f);
    float gy = __fadd_rn(__fmul_rn(f[2 * p + 1], 2.0f), -1.0f);
    float fx = __fmul_rn(__fadd_rn(__fmul_rn(__fadd_rn(gx, 1.0f), (float)GW), -1.0f), 0.5f);
    float fy = __fmul_rn(__fadd_rn(__fmul_rn(__fadd_rn(gy, 1.0f), (float)GW), -1.0f), 0.5f);
    int ix = (int)rintf(fx); ix = ix < 0 ? 0 : (ix > GW - 1 ? GW - 1 : ix);
    int iy = (int)rintf(fy); iy = iy < 0 ? 0 : (iy > GW - 1 ? GW - 1 : iy);
    int base = (iy * 3) * IMGW + ix * 3;   // top-left of 7x7 patch in image
    if (i < NS) g_base_t[p] = base; else g_base_r[p] = base;
}

// ---------------- 2) refer patch channel mean (deterministic tree) ----------------
__global__ void k_mean(const float* __restrict__ rimg) {
    int c = blockIdx.x;                     // 49 blocks
    int off = (c / 7) * IMGW + (c % 7);
    int t = threadIdx.x;
    float s = 0.0f;
    for (int p = t; p < NS; p += 256) s += rimg[g_base_r[p] + off];
    __shared__ float sm[256];
    sm[t] = s; __syncthreads();
    for (int st = 128; st; st >>= 1) { if (t < st) sm[t] += sm[t + st]; __syncthreads(); }
    if (t == 0) g_ymean[c] = sm[0] * (1.0f / (float)NS);
}

// ---------------- 3) centered + L2-normalized feature vectors ----------------
__global__ void k_feat(const float* __restrict__ timg, const float* __restrict__ rimg) {
    int p = blockIdx.x * 256 + threadIdx.x;           // gridDim.x = 25
    bool is_t = (blockIdx.y == 0);
    const float* img = is_t ? timg : rimg;
    int base = is_t ? g_base_t[p] : g_base_r[p];
    float* out = is_t ? g_xf : g_yf;
    float v[CCH];
    float sq = 0.0f;
#pragma unroll
    for (int c = 0; c < CCH; c++) {
        v[c] = img[base + (c / 7) * IMGW + (c % 7)] - g_ymean[c];
        sq += v[c] * v[c];
    }
    float inv = 1.0f / (sqrtf(sq) + EPSF);
#pragma unroll
    for (int c = 0; c < CCH; c++) out[c * NS + p] = v[c] * inv;
}

// ---------------- 4) GEMM: d = max((1 - xf^T yf)/2, 0), store fp16 + row argmin ----------------
// tiles: 128 rows (p) x 128 cols (q), 256 threads, 8x8 micro-tile, dynamic smem
__global__ void __launch_bounds__(256, 2) k_gemm() {
    extern __shared__ float sm[];
    float* As = sm;                // [49][128]
    float* Bs = sm + CCH * 128;    // [49][128]
    int by = blockIdx.y;   // 50 row tiles
    int bx = blockIdx.x;   // 50 col tiles
    int t = threadIdx.x;

    for (int i = t; i < CCH * 32; i += 256) {
        int k = i >> 5, m = (i & 31) << 2;
        *(float4*)&As[k * 128 + m] = *(const float4*)&g_xf[k * NS + by * 128 + m];
        *(float4*)&Bs[k * 128 + m] = *(const float4*)&g_yf[k * NS + bx * 128 + m];
    }
    __syncthreads();

    int tx = t & 15, ty = t >> 4;
    const float* Ap = &As[ty * 8];
    const float* Bp = &Bs[tx * 8];

    float acc[8][8];
#pragma unroll
    for (int i = 0; i < 8; i++)
#pragma unroll
        for (int j = 0; j < 8; j++) acc[i][j] = 0.0f;

#pragma unroll 7
    for (int k = 0; k < CCH; k++) {
        float4 a0 = *(const float4*)(Ap + k * 128);
        float4 a1 = *(const float4*)(Ap + k * 128 + 4);
        float4 b0 = *(const float4*)(Bp + k * 128);
        float4 b1 = *(const float4*)(Bp + k * 128 + 4);
        float a[8] = {a0.x, a0.y, a0.z, a0.w, a1.x, a1.y, a1.z, a1.w};
        float b[8] = {b0.x, b0.y, b0.z, b0.w, b1.x, b1.y, b1.z, b1.w};
#pragma unroll
        for (int i = 0; i < 8; i++)
#pragma unroll
            for (int j = 0; j < 8; j++) acc[i][j] += a[i] * b[j];
    }

    int row0 = by * 128 + ty * 8;
    int col0 = bx * 128 + tx * 8;
#pragma unroll
    for (int i = 0; i < 8; i++) {
        __half hv[8];
        unsigned long long key = ~0ull;
#pragma unroll
        for (int j = 0; j < 8; j++) {
            float sim = acc[i][j];
            float dd = fmaxf(__fmul_rn(__fadd_rn(1.0f, -sim), 0.5f), 0.0f);
            hv[j] = __float2half_rn(dd);
            unsigned long long kk =
                ((unsigned long long)__float_as_uint(dd) << 32) | (unsigned)(col0 + j);
            key = (kk < key) ? kk : key;   // strict <  -> first-index tie break
        }
        *(uint4*)&g_dh[(size_t)(row0 + i) * NS + col0] = *(const uint4*)hv;
#pragma unroll
        for (int off = 8; off; off >>= 1) {
            unsigned long long o = __shfl_down_sync(0xffffffffu, key, off, 16);
            key = (o < key) ? o : key;
        }
        if (tx == 0) atomicMin(&g_amin[row0 + i], key);
    }
}

// ---------------- 5) occurrence counts ----------------
__global__ void k_cnt() {
    int p = blockIdx.x * 256 + threadIdx.x;
    if (p < NS) {
        unsigned q = (unsigned)(g_amin[p] & 0xffffffffu);
        atomicAdd(&g_cnt[q], 1);
    }
}

// ---------------- 6) per-row min + sum-exp -> row loss ----------------
__global__ void __launch_bounds__(256) k_row() {
    __shared__ float sd[NS];        // 25.6 KB: d' row cache
    __shared__ float sr[8];
    int p = blockIdx.x;
    int t = threadIdx.x;
    const uint4* drow = (const uint4*)&g_dh[(size_t)p * NS];   // 8 halves per uint4

    // fused load + occurrence add + partial min
    float m = 3.4e38f;
    for (int j8 = t; j8 < NS / 8; j8 += 256) {
        uint4 u = drow[j8];
        const __half* h = (const __half*)&u;
        int j = j8 * 8;
        float lm = 3.4e38f;
#pragma unroll
        for (int e = 0; e < 8; e++) {
            float v = __half2float(h[e]) + LAMB * (float)g_cnt[j + e];
            sd[j + e] = v;
            lm = fminf(lm, v);
        }
        m = fminf(m, lm);
    }
#pragma unroll
    for (int o = 16; o; o >>= 1) m = fminf(m, __shfl_xor_sync(0xffffffffu, m, o));
    if ((t & 31) == 0) sr[t >> 5] = m;
    __syncthreads();
    if (t == 0) {
        float x = sr[0];
#pragma unroll
        for (int w = 1; w < 8; w++) x = fminf(x, sr[w]);
        sr[0] = x;
    }
    __syncthreads();
    m = sr[0];
    __syncthreads();

    float meps = __fadd_rn(m, EPSF);
    float inv = 1.0f / meps;

    // block sum of w = exp((1 - d'/(m+eps))*2)
    float s = 0.0f;
    for (int j = t; j < NS; j += 256) {
        float r = sd[j] * inv;
        s += __expf(__fmul_rn(__fadd_rn(1.0f, -r), 2.0f));
    }
#pragma unroll
    for (int o = 16; o; o >>= 1) s += __shfl_xor_sync(0xffffffffu, s, o);
    if ((t & 31) == 0) sr[t >> 5] = s;
    __syncthreads();
    if (t == 0) {
        float st = 0.0f;
#pragma unroll
        for (int w = 0; w < 8; w++) st += sr[w];
        float emax = __fmul_rn(__fadd_rn(1.0f, -__fmul_rn(m, inv)), 2.0f);
        g_rowloss[p] = logf(st) - emax;   // -log(CX)
    }
}

// ---------------- 7) final mean ----------------
__global__ void k_final(float* __restrict__ out) {
    int t = threadIdx.x;
    float s = 0.0f;
    for (int p = t; p < NS; p += 256) s += g_rowloss[p];
    __shared__ float sm[256];
    sm[t] = s; __syncthreads();
    for (int st = 128; st; st >>= 1) { if (t < st) sm[t] += sm[t + st]; __syncthreads(); }
    if (t == 0) out[0] = sm[0] * (1.0f / (float)NS);
}

// ---------------- host launch ----------------
extern "C" void kernel_launch(void* const* d_in, const int* in_sizes, int n_in,
                              void* d_out, int out_size) {
    (void)in_sizes; (void)n_in; (void)out_size;
    const float* timg   = (const float*)d_in[0];   // target_features [1,1,512,512]
    const float* rimg   = (const float*)d_in[1];   // refer_features  [1,1,512,512]
    const float* tfield = (const float*)d_in[2];   // target_field [1,80,80,2]
    const float* rfield = (const float*)d_in[3];   // refer_field  [1,80,80,2]
    float* out = (float*)d_out;

    const int GEMM_SMEM = 2 * CCH * 128 * (int)sizeof(float);   // 50176 B
    cudaFuncSetAttribute(k_gemm, cudaFuncAttributeMaxDynamicSharedMemorySize, GEMM_SMEM);

    k_idx  <<<50, 256>>>(tfield, rfield);
    k_mean <<<CCH, 256>>>(rimg);
    k_feat <<<dim3(25, 2), 256>>>(timg, rimg);
    k_gemm <<<dim3(50, 50), 256, GEMM_SMEM>>>();
    k_cnt  <<<25, 256>>>();
    k_row  <<<NS, 256>>>();
    k_final<<<1, 256>>>(out);
}

// round 4
// speedup vs baseline: 1.1117x; 1.0692x over previous
#include <cuda_runtime.h>
#include <cuda_fp16.h>
#include <cstdint>
#include <math.h>

// ---------------- problem constants ----------------
#define NS    6400          // SAMPLE*SAMPLE patches per image
#define CCH   49            // PATCH*PATCH channels
#define IMGW  512
#define GW    169           // (512-7)/3 + 1 patch-grid size
#define EPSF  2.2204460492503131e-16f
#define LAMB  0.05f

// ---------------- device scratch (static; no runtime allocation) ----------------
__device__ int   g_base_t[NS];
__device__ int   g_base_r[NS];
__device__ float g_ymean[CCH];
__device__ float g_xf[CCH * NS];      // [c][p], channel-major
__device__ float g_yf[CCH * NS];
__device__ __half g_dh[(size_t)NS * NS];   // 81.92 MB distance matrix (fp16)
__device__ unsigned long long g_amin[NS];
__device__ int   g_cnt[NS];
__device__ float g_rowloss[NS];

// ---------------- 1) grid-sample nearest indices (+ init amin/cnt) ----------------
__global__ void k_idx(const float* __restrict__ tfield, const float* __restrict__ rfield) {
    int i = blockIdx.x * blockDim.x + threadIdx.x;
    if (i < NS) { g_amin[i] = ~0ull; g_cnt[i] = 0; }
    if (i >= 2 * NS) return;
    const float* f = (i < NS) ? tfield : rfield;
    int p = (i < NS) ? i : (i - NS);
    float gx = __fadd_rn(__fmul_rn(f[2 * p + 0], 2.0f), -1.0f);
    float gy = __fadd_rn(__fmul_rn(f[2 * p + 1], 2.0f), -1.0f);
    float fx = __fmul_rn(__fadd_rn(__fmul_rn(__fadd_rn(gx, 1.0f), (float)GW), -1.0f), 0.5f);
    float fy = __fmul_rn(__fadd_rn(__fmul_rn(__fadd_rn(gy, 1.0f), (float)GW), -1.0f), 0.5f);
    int ix = (int)rintf(fx); ix = ix < 0 ? 0 : (ix > GW - 1 ? GW - 1 : ix);
    int iy = (int)rintf(fy); iy = iy < 0 ? 0 : (iy > GW - 1 ? GW - 1 : iy);
    int base = (iy * 3) * IMGW + ix * 3;   // top-left of 7x7 patch in image
    if (i < NS) g_base_t[p] = base; else g_base_r[p] = base;
}

// ---------------- 2) refer patch channel mean (deterministic tree) ----------------
__global__ void k_mean(const float* __restrict__ rimg) {
    int c = blockIdx.x;                     // 49 blocks
    int off = (c / 7) * IMGW + (c % 7);
    int t = threadIdx.x;
    float s = 0.0f;
    for (int p = t; p < NS; p += 256) s += rimg[g_base_r[p] + off];
    __shared__ float sm[256];
    sm[t] = s; __syncthreads();
    for (int st = 128; st; st >>= 1) { if (t < st) sm[t] += sm[t + st]; __syncthreads(); }
    if (t == 0) g_ymean[c] = sm[0] * (1.0f / (float)NS);
}

// ---------------- 3) centered + L2-normalized feature vectors ----------------
__global__ void k_feat(const float* __restrict__ timg, const float* __restrict__ rimg) {
    int p = blockIdx.x * 256 + threadIdx.x;           // gridDim.x = 25
    bool is_t = (blockIdx.y == 0);
    const float* img = is_t ? timg : rimg;
    int base = is_t ? g_base_t[p] : g_base_r[p];
    float* out = is_t ? g_xf : g_yf;
    float v[CCH];
    float sq = 0.0f;
#pragma unroll
    for (int c = 0; c < CCH; c++) {
        v[c] = img[base + (c / 7) * IMGW + (c % 7)] - g_ymean[c];
        sq += v[c] * v[c];
    }
    float inv = 1.0f / (sqrtf(sq) + EPSF);
#pragma unroll
    for (int c = 0; c < CCH; c++) out[c * NS + p] = v[c] * inv;
}

// ---------------- 4) GEMM via packed fma.rn.f32x2 ----------------
// d = max((1 - xf^T yf)/2, 0), store fp16 + row argmin
// tiles: 128x128, 256 threads, 8x8 micro-tile; accumulators packed pairwise over j
__global__ void __launch_bounds__(256, 2) k_gemm() {
    extern __shared__ float sm[];
    float* As = sm;                // [49][128]
    float* Bs = sm + CCH * 128;    // [49][128]
    int by = blockIdx.y;
    int bx = blockIdx.x;
    int t = threadIdx.x;

    for (int i = t; i < CCH * 32; i += 256) {
        int k = i >> 5, m = (i & 31) << 2;
        *(float4*)&As[k * 128 + m] = *(const float4*)&g_xf[k * NS + by * 128 + m];
        *(float4*)&Bs[k * 128 + m] = *(const float4*)&g_yf[k * NS + bx * 128 + m];
    }
    __syncthreads();

    int tx = t & 15, ty = t >> 4;
    const float* Ap = &As[ty * 8];
    const float* Bp = &Bs[tx * 8];

    // acc2[i][j]: packed pair (col 2j, col 2j+1) for row i
    unsigned long long acc2[8][4];
#pragma unroll
    for (int i = 0; i < 8; i++)
#pragma unroll
        for (int j = 0; j < 4; j++) acc2[i][j] = 0ull;

#pragma unroll 7
    for (int k = 0; k < CCH; k++) {
        const float* ap = Ap + k * 128;
        const float* bp = Bp + k * 128;
        // B: 8 floats = 4 packed f32x2 pairs, loaded directly as 64-bit lanes
        double2 q0 = *(const double2*)bp;          // b[0..3]
        double2 q1 = *(const double2*)(bp + 8 / 2 * 0 + 4);  // b[4..7]
        unsigned long long b2[4] = {
            __double_as_longlong(q0.x), __double_as_longlong(q0.y),
            __double_as_longlong(q1.x), __double_as_longlong(q1.y)};
        float4 a0 = *(const float4*)ap;
        float4 a1 = *(const float4*)(ap + 4);
        float a[8] = {a0.x, a0.y, a0.z, a0.w, a1.x, a1.y, a1.z, a1.w};
        unsigned long long a2[8];
#pragma unroll
        for (int i = 0; i < 8; i++)
            asm("mov.b64 %0, {%1, %1};" : "=l"(a2[i]) : "f"(a[i]));
#pragma unroll
        for (int i = 0; i < 8; i++)
#pragma unroll
            for (int j = 0; j < 4; j++)
                asm("fma.rn.f32x2 %0, %1, %2, %0;"
                    : "+l"(acc2[i][j]) : "l"(a2[i]), "l"(b2[j]));
    }

    int row0 = by * 128 + ty * 8;
    int col0 = bx * 128 + tx * 8;
#pragma unroll
    for (int i = 0; i < 8; i++) {
        __half hv[8];
        unsigned long long key = ~0ull;
#pragma unroll
        for (int j = 0; j < 4; j++) {
            unsigned lo, hi;
            asm("mov.b64 {%0, %1}, %2;" : "=r"(lo), "=r"(hi) : "l"(acc2[i][j]));
            float s0 = __uint_as_float(lo), s1 = __uint_as_float(hi);
            float d0 = fmaxf(__fmul_rn(__fadd_rn(1.0f, -s0), 0.5f), 0.0f);
            float d1 = fmaxf(__fmul_rn(__fadd_rn(1.0f, -s1), 0.5f), 0.0f);
            hv[2 * j]     = __float2half_rn(d0);
            hv[2 * j + 1] = __float2half_rn(d1);
            unsigned long long k0 =
                ((unsigned long long)__float_as_uint(d0) << 32) | (unsigned)(col0 + 2 * j);
            unsigned long long k1 =
                ((unsigned long long)__float_as_uint(d1) << 32) | (unsigned)(col0 + 2 * j + 1);
            key = (k0 < key) ? k0 : key;
            key = (k1 < key) ? k1 : key;   // strict < -> first-index tie break
        }
        *(uint4*)&g_dh[(size_t)(row0 + i) * NS + col0] = *(const uint4*)hv;
#pragma unroll
        for (int off = 8; off; off >>= 1) {
            unsigned long long o = __shfl_down_sync(0xffffffffu, key, off, 16);
            key = (o < key) ? o : key;
        }
        if (tx == 0) atomicMin(&g_amin[row0 + i], key);
    }
}

// ---------------- 5) occurrence counts ----------------
__global__ void k_cnt() {
    int p = blockIdx.x * 256 + threadIdx.x;
    if (p < NS) {
        unsigned q = (unsigned)(g_amin[p] & 0xffffffffu);
        atomicAdd(&g_cnt[q], 1);
    }
}

// ---------------- 6) per-row min + sum-exp -> row loss ----------------
__global__ void __launch_bounds__(256) k_row() {
    __shared__ float sd[NS];        // 25.6 KB: d' row cache
    __shared__ float sr[8];
    int p = blockIdx.x;
    int t = threadIdx.x;
    const uint4* drow = (const uint4*)&g_dh[(size_t)p * NS];   // 8 halves per uint4

    float m = 3.4e38f;
    for (int j8 = t; j8 < NS / 8; j8 += 256) {
        uint4 u = drow[j8];
        const __half* h = (const __half*)&u;
        int j = j8 * 8;
        float lm = 3.4e38f;
#pragma unroll
        for (int e = 0; e < 8; e++) {
            float v = __half2float(h[e]) + LAMB * (float)g_cnt[j + e];
            sd[j + e] = v;
            lm = fminf(lm, v);
        }
        m = fminf(m, lm);
    }
#pragma unroll
    for (int o = 16; o; o >>= 1) m = fminf(m, __shfl_xor_sync(0xffffffffu, m, o));
    if ((t & 31) == 0) sr[t >> 5] = m;
    __syncthreads();
    if (t == 0) {
        float x = sr[0];
#pragma unroll
        for (int w = 1; w < 8; w++) x = fminf(x, sr[w]);
        sr[0] = x;
    }
    __syncthreads();
    m = sr[0];
    __syncthreads();

    float meps = __fadd_rn(m, EPSF);
    float inv = 1.0f / meps;

    float s = 0.0f;
    for (int j = t; j < NS; j += 256) {
        float r = sd[j] * inv;
        s += __expf(__fmul_rn(__fadd_rn(1.0f, -r), 2.0f));
    }
#pragma unroll
    for (int o = 16; o; o >>= 1) s += __shfl_xor_sync(0xffffffffu, s, o);
    if ((t & 31) == 0) sr[t >> 5] = s;
    __syncthreads();
    if (t == 0) {
        float st = 0.0f;
#pragma unroll
        for (int w = 0; w < 8; w++) st += sr[w];
        float emax = __fmul_rn(__fadd_rn(1.0f, -__fmul_rn(m, inv)), 2.0f);
        g_rowloss[p] = logf(st) - emax;   // -log(CX)
    }
}

// ---------------- 7) final mean ----------------
__global__ void k_final(float* __restrict__ out) {
    int t = threadIdx.x;
    float s = 0.0f;
    for (int p = t; p < NS; p += 256) s += g_rowloss[p];
    __shared__ float sm[256];
    sm[t] = s; __syncthreads();
    for (int st = 128; st; st >>= 1) { if (t < st) sm[t] += sm[t + st]; __syncthreads(); }
    if (t == 0) out[0] = sm[0] * (1.0f / (float)NS);
}

// ---------------- host launch ----------------
extern "C" void kernel_launch(void* const* d_in, const int* in_sizes, int n_in,
                              void* d_out, int out_size) {
    (void)in_sizes; (void)n_in; (void)out_size;
    const float* timg   = (const float*)d_in[0];   // target_features [1,1,512,512]
    const float* rimg   = (const float*)d_in[1];   // refer_features  [1,1,512,512]
    const float* tfield = (const float*)d_in[2];   // target_field [1,80,80,2]
    const float* rfield = (const float*)d_in[3];   // refer_field  [1,80,80,2]
    float* out = (float*)d_out;

    const int GEMM_SMEM = 2 * CCH * 128 * (int)sizeof(float);   // 50176 B
    cudaFuncSetAttribute(k_gemm, cudaFuncAttributeMaxDynamicSharedMemorySize, GEMM_SMEM);

    k_idx  <<<50, 256>>>(tfield, rfield);
    k_mean <<<CCH, 256>>>(rimg);
    k_feat <<<dim3(25, 2), 256>>>(timg, rimg);
    k_gemm <<<dim3(50, 50), 256, GEMM_SMEM>>>();
    k_cnt  <<<25, 256>>>();
    k_row  <<<NS, 256>>>();
    k_final<<<1, 256>>>(out);
}

// round 6
// speedup vs baseline: 1.1119x; 1.0002x over previous
#include <cuda_runtime.h>
#include <cuda_fp16.h>
#include <cstdint>
#include <math.h>

// ---------------- problem constants ----------------
#define NS    6400          // SAMPLE*SAMPLE patches per image
#define CCH   49            // PATCH*PATCH channels
#define IMGW  512
#define GW    169           // (512-7)/3 + 1 patch-grid size
#define EPSF  2.2204460492503131e-16f
#define LAMB  0.05f

// ---------------- device scratch (static; no runtime allocation) ----------------
__device__ int   g_base_t[NS];
__device__ int   g_base_r[NS];
__device__ float g_ymean[CCH];
__device__ float g_xf[CCH * NS];      // [c][p], channel-major
__device__ float g_yf[CCH * NS];
__device__ __half g_dh[(size_t)NS * NS];   // 81.92 MB distance matrix (fp16)
__device__ unsigned long long g_amin[NS];
__device__ int   g_cnt[NS];
__device__ float g_rowloss[NS];

// ---------------- 1) grid-sample nearest indices (+ init amin/cnt) ----------------
__global__ void k_idx(const float* __restrict__ tfield, const float* __restrict__ rfield) {
    int i = blockIdx.x * blockDim.x + threadIdx.x;
    if (i < NS) { g_amin[i] = ~0ull; g_cnt[i] = 0; }
    if (i >= 2 * NS) return;
    const float* f = (i < NS) ? tfield : rfield;
    int p = (i < NS) ? i : (i - NS);
    float gx = __fadd_rn(__fmul_rn(f[2 * p + 0], 2.0f), -1.0f);
    float gy = __fadd_rn(__fmul_rn(f[2 * p + 1], 2.0f), -1.0f);
    float fx = __fmul_rn(__fadd_rn(__fmul_rn(__fadd_rn(gx, 1.0f), (float)GW), -1.0f), 0.5f);
    float fy = __fmul_rn(__fadd_rn(__fmul_rn(__fadd_rn(gy, 1.0f), (float)GW), -1.0f), 0.5f);
    int ix = (int)rintf(fx); ix = ix < 0 ? 0 : (ix > GW - 1 ? GW - 1 : ix);
    int iy = (int)rintf(fy); iy = iy < 0 ? 0 : (iy > GW - 1 ? GW - 1 : iy);
    int base = (iy * 3) * IMGW + ix * 3;   // top-left of 7x7 patch in image
    if (i < NS) g_base_t[p] = base; else g_base_r[p] = base;
}

// ---------------- 2) refer patch channel mean (deterministic tree) ----------------
__global__ void k_mean(const float* __restrict__ rimg) {
    int c = blockIdx.x;                     // 49 blocks
    int off = (c / 7) * IMGW + (c % 7);
    int t = threadIdx.x;
    float s = 0.0f;
    for (int p = t; p < NS; p += 256) s += rimg[g_base_r[p] + off];
    __shared__ float sm[256];
    sm[t] = s; __syncthreads();
    for (int st = 128; st; st >>= 1) { if (t < st) sm[t] += sm[t + st]; __syncthreads(); }
    if (t == 0) g_ymean[c] = sm[0] * (1.0f / (float)NS);
}

// ---------------- 3) centered + L2-normalized feature vectors ----------------
__global__ void k_feat(const float* __restrict__ timg, const float* __restrict__ rimg) {
    int p = blockIdx.x * 256 + threadIdx.x;           // gridDim.x = 25
    bool is_t = (blockIdx.y == 0);
    const float* img = is_t ? timg : rimg;
    int base = is_t ? g_base_t[p] : g_base_r[p];
    float* out = is_t ? g_xf : g_yf;
    float v[CCH];
    float sq = 0.0f;
#pragma unroll
    for (int c = 0; c < CCH; c++) {
        v[c] = img[base + (c / 7) * IMGW + (c % 7)] - g_ymean[c];
        sq += v[c] * v[c];
    }
    float inv = 1.0f / (sqrtf(sq) + EPSF);
#pragma unroll
    for (int c = 0; c < CCH; c++) out[c * NS + p] = v[c] * inv;
}

// ---------------- 4) GEMM via packed fma.rn.f32x2 ----------------
// d = max((1 - xf^T yf)/2, 0), store fp16 + row argmin
// tiles: 128x128, 256 threads, 8x8 micro-tile; accumulators packed pairwise over j
__global__ void __launch_bounds__(256, 2) k_gemm() {
    extern __shared__ float sm[];
    float* As = sm;                // [49][128]
    float* Bs = sm + CCH * 128;    // [49][128]
    int by = blockIdx.y;
    int bx = blockIdx.x;
    int t = threadIdx.x;

    for (int i = t; i < CCH * 32; i += 256) {
        int k = i >> 5, m = (i & 31) << 2;
        *(float4*)&As[k * 128 + m] = *(const float4*)&g_xf[k * NS + by * 128 + m];
        *(float4*)&Bs[k * 128 + m] = *(const float4*)&g_yf[k * NS + bx * 128 + m];
    }
    __syncthreads();

    int tx = t & 15, ty = t >> 4;
    const float* Ap = &As[ty * 8];
    const float* Bp = &Bs[tx * 8];

    // acc2[i][j]: packed pair (col 2j, col 2j+1) for row i
    unsigned long long acc2[8][4];
#pragma unroll
    for (int i = 0; i < 8; i++)
#pragma unroll
        for (int j = 0; j < 4; j++) acc2[i][j] = 0ull;

#pragma unroll 7
    for (int k = 0; k < CCH; k++) {
        const float* ap = Ap + k * 128;
        const float* bp = Bp + k * 128;
        double2 q0 = *(const double2*)bp;          // b[0..3]
        double2 q1 = *(const double2*)(bp + 4);    // b[4..7]
        unsigned long long b2[4] = {
            (unsigned long long)__double_as_longlong(q0.x),
            (unsigned long long)__double_as_longlong(q0.y),
            (unsigned long long)__double_as_longlong(q1.x),
            (unsigned long long)__double_as_longlong(q1.y)};
        float4 a0 = *(const float4*)ap;
        float4 a1 = *(const float4*)(ap + 4);
        float a[8] = {a0.x, a0.y, a0.z, a0.w, a1.x, a1.y, a1.z, a1.w};
        unsigned long long a2[8];
#pragma unroll
        for (int i = 0; i < 8; i++)
            asm("mov.b64 %0, {%1, %1};" : "=l"(a2[i]) : "f"(a[i]));
#pragma unroll
        for (int i = 0; i < 8; i++)
#pragma unroll
            for (int j = 0; j < 4; j++)
                asm("fma.rn.f32x2 %0, %1, %2, %0;"
                    : "+l"(acc2[i][j]) : "l"(a2[i]), "l"(b2[j]));
    }

    int row0 = by * 128 + ty * 8;
    int col0 = bx * 128 + tx * 8;
#pragma unroll
    for (int i = 0; i < 8; i++) {
        __half hv[8];
        unsigned long long key = ~0ull;
#pragma unroll
        for (int j = 0; j < 4; j++) {
            unsigned lo, hi;
            asm("mov.b64 {%0, %1}, %2;" : "=r"(lo), "=r"(hi) : "l"(acc2[i][j]));
            float s0 = __uint_as_float(lo), s1 = __uint_as_float(hi);
            float d0 = fmaxf(__fmul_rn(__fadd_rn(1.0f, -s0), 0.5f), 0.0f);
            float d1 = fmaxf(__fmul_rn(__fadd_rn(1.0f, -s1), 0.5f), 0.0f);
            hv[2 * j]     = __float2half_rn(d0);
            hv[2 * j + 1] = __float2half_rn(d1);
            unsigned long long k0 =
                ((unsigned long long)__float_as_uint(d0) << 32) | (unsigned)(col0 + 2 * j);
            unsigned long long k1 =
                ((unsigned long long)__float_as_uint(d1) << 32) | (unsigned)(col0 + 2 * j + 1);
            key = (k0 < key) ? k0 : key;
            key = (k1 < key) ? k1 : key;   // strict < -> first-index tie break
        }
        *(uint4*)&g_dh[(size_t)(row0 + i) * NS + col0] = *(const uint4*)hv;
#pragma unroll
        for (int off = 8; off; off >>= 1) {
            unsigned long long o = __shfl_down_sync(0xffffffffu, key, off, 16);
            key = (o < key) ? o : key;
        }
        if (tx == 0) atomicMin(&g_amin[row0 + i], key);
    }
}

// ---------------- 5) occurrence counts ----------------
__global__ void k_cnt() {
    int p = blockIdx.x * 256 + threadIdx.x;
    if (p < NS) {
        unsigned q = (unsigned)(g_amin[p] & 0xffffffffu);
        atomicAdd(&g_cnt[q], 1);
    }
}

// ---------------- 6) per-row min + sum-exp -> row loss (8 rows per block) ----------------
// dynamic smem: occ[NS] + sd[NS] + sr[8]  = 51232 bytes
__global__ void __launch_bounds__(256) k_row() {
    extern __shared__ float dyn[];
    float* occ = dyn;               // [NS] 0.05*cnt, loaded once per block
    float* sd  = dyn + NS;          // [NS] d' row cache, reused across 8 rows
    float* sr  = dyn + 2 * NS;      // [8]
    int t = threadIdx.x;

    for (int j = t; j < NS; j += 256) occ[j] = LAMB * (float)g_cnt[j];
    __syncthreads();

#pragma unroll 1
    for (int r = 0; r < 8; r++) {
        int p = blockIdx.x * 8 + r;
        const uint4* drow = (const uint4*)&g_dh[(size_t)p * NS];   // 8 halves per uint4

        // pass 1: load + occurrence add + partial min
        float m = 3.4e38f;
        for (int j8 = t; j8 < NS / 8; j8 += 256) {
            uint4 u = drow[j8];
            const __half* h = (const __half*)&u;
            int j = j8 * 8;
            float lm = 3.4e38f;
#pragma unroll
            for (int e = 0; e < 8; e++) {
                float v = __half2float(h[e]) + occ[j + e];
                sd[j + e] = v;
                lm = fminf(lm, v);
            }
            m = fminf(m, lm);
        }
#pragma unroll
        for (int o = 16; o; o >>= 1) m = fminf(m, __shfl_xor_sync(0xffffffffu, m, o));
        if ((t & 31) == 0) sr[t >> 5] = m;
        __syncthreads();
        if (t == 0) {
            float x = sr[0];
#pragma unroll
            for (int w = 1; w < 8; w++) x = fminf(x, sr[w]);
            sr[0] = x;
        }
        __syncthreads();
        m = sr[0];
        __syncthreads();

        float meps = __fadd_rn(m, EPSF);
        float inv = 1.0f / meps;

        // pass 2: sum of w = exp((1 - d'/(m+eps))*2)
        float s = 0.0f;
        for (int j = t; j < NS; j += 256) {
            float rr = sd[j] * inv;
            s += __expf(__fmul_rn(__fadd_rn(1.0f, -rr), 2.0f));
        }
#pragma unroll
        for (int o = 16; o; o >>= 1) s += __shfl_xor_sync(0xffffffffu, s, o);
        if ((t & 31) == 0) sr[t >> 5] = s;
        __syncthreads();
        if (t == 0) {
            float st = 0.0f;
#pragma unroll
            for (int w = 0; w < 8; w++) st += sr[w];
            float emax = __fmul_rn(__fadd_rn(1.0f, -__fmul_rn(m, inv)), 2.0f);
            g_rowloss[p] = logf(st) - emax;   // -log(CX)
        }
        __syncthreads();   // protect sd/sr reuse across rows
    }
}

// ---------------- 7) final mean ----------------
__global__ void k_final(float* __restrict__ out) {
    int t = threadIdx.x;
    float s = 0.0f;
    for (int p = t; p < NS; p += 256) s += g_rowloss[p];
    __shared__ float sm[256];
    sm[t] = s; __syncthreads();
    for (int st = 128; st; st >>= 1) { if (t < st) sm[t] += sm[t + st]; __syncthreads(); }
    if (t == 0) out[0] = sm[0] * (1.0f / (float)NS);
}

// ---------------- host launch ----------------
extern "C" void kernel_launch(void* const* d_in, const int* in_sizes, int n_in,
                              void* d_out, int out_size) {
    (void)in_sizes; (void)n_in; (void)out_size;
    const float* timg   = (const float*)d_in[0];   // target_features [1,1,512,512]
    const float* rimg   = (const float*)d_in[1];   // refer_features  [1,1,512,512]
    const float* tfield = (const float*)d_in[2];   // target_field [1,80,80,2]
    const float* rfield = (const float*)d_in[3];   // refer_field  [1,80,80,2]
    float* out = (float*)d_out;

    const int GEMM_SMEM = 2 * CCH * 128 * (int)sizeof(float);        // 50176 B
    const int ROW_SMEM  = (2 * NS + 8) * (int)sizeof(float);         // 51232 B
    cudaFuncSetAttribute(k_gemm, cudaFuncAttributeMaxDynamicSharedMemorySize, GEMM_SMEM);
    cudaFuncSetAttribute(k_row,  cudaFuncAttributeMaxDynamicSharedMemorySize, ROW_SMEM);

    k_idx  <<<50, 256>>>(tfield, rfield);
    k_mean <<<CCH, 256>>>(rimg);
    k_feat <<<dim3(25, 2), 256>>>(timg, rimg);
    k_gemm <<<dim3(50, 50), 256, GEMM_SMEM>>>();
    k_cnt  <<<25, 256>>>();
    k_row  <<<800, 256, ROW_SMEM>>>();
    k_final<<<1, 256>>>(out);
}